// round 8
// baseline (speedup 1.0000x reference)
#include <cuda_runtime.h>
#include <cstdint>

// ROI-align pooling R7: locality-scheduled persistent blocks.
// Bins sorted by anchor-pixel Morton tile (8x8 px, 256 buckets, counting
// sort) so bins reading the same image pixels run temporally adjacent on the
// SAME SM -> L1D (228KB, persists within launch) serves the ~2.7x inter-ROI
// read redundancy instead of L2 (which is the binding resource at ~10.3TB/s).
// Main kernel: 1184 persistent blocks, each a contiguous ~11-bin sorted
// chunk, R4 per-bin body (4 front-batched LDG.128 + 24 FFMA + STG.128),
// low regs -> full 8-block occupancy.

#define POOL  7
#define NROIS 256
#define HH    128
#define WW    128
#define CC    1024
#define NBINS (NROIS * POOL * POOL)   // 12544
#define NPB   1184                    // persistent blocks (148 SM x 8)

__device__ int4           g_offs[NBINS];
__device__ float2         g_ts[NBINS];
__device__ unsigned char  g_key[NBINS];
__device__ int            g_hist[256];
__device__ int            g_base[256];
__device__ int            g_cursor[256];
__device__ unsigned short g_order[NBINS];

__global__ void zero_kernel()
{
    const int t = threadIdx.x;
    g_hist[t] = 0;
    g_cursor[t] = 0;
}

__device__ __forceinline__ unsigned spread4(unsigned x)
{
    x = (x | (x << 2)) & 0x33u;
    x = (x | (x << 1)) & 0x55u;
    return x;
}

__global__ void setup_kernel(const float* __restrict__ rois)
{
    const int bin = blockIdx.x * blockDim.x + threadIdx.x;
    if (bin >= NBINS) return;

    const int roi = bin / (POOL * POOL);
    const int b49 = bin - roi * (POOL * POOL);
    const int iy  = b49 / POOL;
    const int ix  = b49 - iy * POOL;

    const float4 r = reinterpret_cast<const float4*>(rois)[roi];
    const int x0 = (int)(r.x * 0.0625f);
    const int y0 = (int)(r.y * 0.0625f);
    const int w  = (int)(r.z * 0.0625f);
    const int h  = (int)(r.w * 0.0625f);

    // identical fp32 math to reference
    const float sy = (float)iy * ((float)h / (float)POOL);
    const float sx = (float)ix * ((float)w / (float)POOL);
    const float fy = floorf(sy);
    const float fx = floorf(sx);
    const float ty = sy - fy;
    const float tx = sx - fx;

    const int y_lo = (int)fy;
    const int x_lo = (int)fx;
    const int y_hi = min(y_lo + 1, max(h - 1, 0));
    const int x_hi = min(x_lo + 1, max(w - 1, 0));

    const int gy0 = min(max(y0 + y_lo, 0), HH - 1);
    const int gy1 = min(max(y0 + y_hi, 0), HH - 1);
    const int gx0 = min(max(x0 + x_lo, 0), WW - 1);
    const int gx1 = min(max(x0 + x_hi, 0), WW - 1);

    // Fold dead-weight (t==0) / clamp-identical hi corners onto lo corner
    // (bit-exact; removes genuinely dead L2 traffic).
    const int ex = (tx != 0.0f && gx1 != gx0) ? gx1 : gx0;
    const int ey = (ty != 0.0f && gy1 != gy0) ? gy1 : gy0;

    const int c4 = CC / 4;
    int4 o;
    o.x = (gy0 * WW + gx0) * c4;
    o.y = (gy0 * WW + ex ) * c4;
    o.z = (ey  * WW + gx0) * c4;
    o.w = (ey  * WW + ex ) * c4;
    g_offs[bin] = o;
    g_ts[bin]   = make_float2(tx, ty);

    // Morton key of the anchor pixel's 8x8 tile (16x16 tiles -> 256 buckets).
    const unsigned kx = (unsigned)gx0 >> 3;
    const unsigned ky = (unsigned)gy0 >> 3;
    const unsigned char key = (unsigned char)((spread4(ky) << 1) | spread4(kx));
    g_key[bin] = key;
    atomicAdd(&g_hist[key], 1);
}

__global__ void scan_kernel()
{
    // 256-element exclusive scan, one block of 256 threads.
    __shared__ int s[256];
    const int t = threadIdx.x;
    s[t] = g_hist[t];
    __syncthreads();
    int v = s[t];
    for (int d = 1; d < 256; d <<= 1) {
        int add = (t >= d) ? s[t - d] : 0;
        __syncthreads();
        s[t] = v = v + add;
        __syncthreads();
    }
    g_base[t] = v - g_hist[t];   // exclusive
}

__global__ void scatter_kernel()
{
    const int bin = blockIdx.x * blockDim.x + threadIdx.x;
    if (bin >= NBINS) return;
    const int k = g_key[bin];
    const int pos = g_base[k] + atomicAdd(&g_cursor[k], 1);
    g_order[pos] = (unsigned short)bin;
}

__global__ __launch_bounds__(256, 8)
void roi_pool_kernel(const float* __restrict__ img,
                     float* __restrict__ out)
{
    const int t = threadIdx.x;
    const float4* __restrict__ imgv = reinterpret_cast<const float4*>(img);
    float4* __restrict__ outv = reinterpret_cast<float4*>(out);

    // Interleaved chunk id: co-resident blocks (same bid%148 residue -> same
    // SM in wave-1 placement) get ADJACENT sorted chunks, widening the
    // same-SM locality window to ~88 bins.
    const int cid = (blockIdx.x % 148) * 8 + blockIdx.x / 148;   // 0..1183
    const int lo  = (int)((long long)cid * NBINS / NPB);
    const int hi  = (int)((long long)(cid + 1) * NBINS / NPB);

    for (int i = lo; i < hi; i++) {
        const int bin = g_order[i];

        const int4   o  = g_offs[bin];
        const float2 tw = g_ts[bin];
        const float  tx = tw.x, ty = tw.y;

        // 4 unconditional front-batched LDG.128 (locality -> many L1 hits)
        const float4 a = imgv[o.x + t];
        const float4 b = imgv[o.y + t];
        const float4 c = imgv[o.z + t];
        const float4 d = imgv[o.w + t];

        float4 r;
        {
            float top, bot;
            top = a.x + tx * (b.x - a.x);
            bot = c.x + tx * (d.x - c.x);
            r.x = top + ty * (bot - top);
            top = a.y + tx * (b.y - a.y);
            bot = c.y + tx * (d.y - c.y);
            r.y = top + ty * (bot - top);
            top = a.z + tx * (b.z - a.z);
            bot = c.z + tx * (d.z - c.z);
            r.z = top + ty * (bot - top);
            top = a.w + tx * (b.w - a.w);
            bot = c.w + tx * (d.w - c.w);
            r.w = top + ty * (bot - top);
        }
        outv[(size_t)bin * (CC / 4) + t] = r;
    }
}

extern "C" void kernel_launch(void* const* d_in, const int* in_sizes, int n_in,
                              void* d_out, int out_size)
{
    const float* img  = (const float*)d_in[0];
    const float* rois = (const float*)d_in[1];
    if (n_in >= 2 && in_sizes[0] < in_sizes[1]) {
        img  = (const float*)d_in[1];
        rois = (const float*)d_in[0];
    }
    float* out = (float*)d_out;

    zero_kernel<<<1, 256>>>();
    setup_kernel<<<(NBINS + 255) / 256, 256>>>(rois);
    scan_kernel<<<1, 256>>>();
    scatter_kernel<<<(NBINS + 255) / 256, 256>>>();
    roi_pool_kernel<<<NPB, 256>>>(img, out);
}